// round 7
// baseline (speedup 1.0000x reference)
#include <cuda_runtime.h>
#include <math.h>

#define T 32768
#define D 1024
#define L 32                  // steps per chunk
#define NCHUNK (T / L)        // 1024

#define ETA_MU  0.01f
#define ETA_VAR 0.02f

// Per-(chunk, col) scratch, [chunk][col] layout: 4MB each.
static __device__ float g_sum  [NCHUNK * D];
static __device__ float g_sumsq[NCHUNK * D];
static __device__ float g_smu  [NCHUNK * D];
static __device__ float g_A    [NCHUNK * D];
static __device__ float g_B    [NCHUNK * D];
static __device__ float g_muin [NCHUNK * D];
static __device__ float g_varin[NCHUNK * D];

// ---------------------------------------------------------------------------
// Pass B: one streaming read of x (float4/thread = 4 cols; 256 thr = all of D).
// Per (chunk, col): sum, sumsq (global stats), S_mu (zero-carry local mu scan),
// A, B with  S_var(mu_in) = A - B*mu_in + Cc*mu_in^2  (Cc data-independent).
// NCHUNK=1024 blocks -> ~7 waves on 148 SMs: minimal wave-quantization tail.
// ---------------------------------------------------------------------------
__global__ void __launch_bounds__(256) pass_b(const float* __restrict__ x) {
    const int col4 = threadIdx.x;
    const int c    = blockIdx.x;
    const float4* __restrict__ xp =
        (const float4*)(x + (size_t)c * L * D) + col4;

    float4 sum   = {0,0,0,0}, sumsq = {0,0,0,0};
    float4 s     = {0,0,0,0};
    float4 A     = {0,0,0,0}, Bc    = {0,0,0,0};
    float  p     = 1.f;

    #pragma unroll 8
    for (int i = 0; i < L; i++) {
        float4 xv = __ldcs(&xp[(size_t)i * (D / 4)]);
        p *= (1.0f - ETA_MU);
        const float twoEtaP = (2.0f * ETA_VAR) * p;

        #define STEP(f)                                                     \
        {                                                                   \
            sum.f  += xv.f;                                                 \
            sumsq.f = fmaf(xv.f, xv.f, sumsq.f);                            \
            s.f     = fmaf(ETA_MU, xv.f - s.f, s.f);                        \
            float e = xv.f - s.f;                                           \
            A.f     = fmaf(1.0f - ETA_VAR, A.f,  ETA_VAR * e * e);          \
            Bc.f    = fmaf(1.0f - ETA_VAR, Bc.f, twoEtaP * e);              \
        }
        STEP(x) STEP(y) STEP(z) STEP(w)
        #undef STEP
    }
    const int idx4 = c * (D / 4) + col4;
    ((float4*)g_sum)  [idx4] = sum;
    ((float4*)g_sumsq)[idx4] = sumsq;
    ((float4*)g_smu)  [idx4] = s;
    ((float4*)g_A)    [idx4] = A;
    ((float4*)g_B)    [idx4] = Bc;
}

// ---------------------------------------------------------------------------
// Pass C: 64 blocks x 256 threads; block owns 16 columns.
//  1) cooperatively stage A/B/S for its columns into SMEM (192KB)
//  2) parallel sum/sumsq reduction -> mu0, unbiased-std0 (torch.std quirk)
//  3) 16 threads run the serial 1024-chunk carry recurrence from SMEM
// ---------------------------------------------------------------------------
#define CPB 16                          // columns per block
#define PC_THREADS 256
#define RED_GRP 16                      // chunk groups for the reduction

__global__ void __launch_bounds__(PC_THREADS) pass_c() {
    extern __shared__ float smem[];
    float* sA   = smem;                         // [NCHUNK][CPB]
    float* sB   = sA + NCHUNK * CPB;
    float* sS   = sB + NCHUNK * CPB;
    float* red  = sS + NCHUNK * CPB;            // [RED_GRP][CPB] x2

    const int tid  = threadIdx.x;
    const int col0 = blockIdx.x * CPB;

    for (int i = tid; i < NCHUNK * CPB; i += PC_THREADS) {
        const int chunk = i / CPB;
        const int lc    = i % CPB;
        const int gidx  = chunk * D + col0 + lc;
        sA[i] = __ldg(&g_A[gidx]);
        sB[i] = __ldg(&g_B[gidx]);
        sS[i] = __ldg(&g_smu[gidx]);
    }

    {
        const int lc  = tid % CPB;
        const int grp = tid / CPB;
        const int cpg = NCHUNK / RED_GRP;
        float ps = 0.f, pq = 0.f;
        for (int c = grp * cpg; c < (grp + 1) * cpg; c++) {
            ps += __ldg(&g_sum  [c * D + col0 + lc]);
            pq += __ldg(&g_sumsq[c * D + col0 + lc]);
        }
        red[grp * CPB + lc]                  = ps;
        red[RED_GRP * CPB + grp * CPB + lc]  = pq;
    }
    __syncthreads();

    if (tid < CPB) {
        const int col = col0 + tid;

        float sum = 0.f, sumsq = 0.f;
        #pragma unroll
        for (int g = 0; g < RED_GRP; g++) {
            sum   += red[g * CPB + tid];
            sumsq += red[RED_GRP * CPB + g * CPB + tid];
        }
        const float mu0  = sum / (float)T;
        const float var0 = (sumsq - sum * mu0) / (float)(T - 1);
        const float std0 = sqrtf(fmaxf(var0, 0.0f));

        // Cc = sum_i 0.98^{L-1-i} * 0.02 * (0.99^{i+1})^2   (constant)
        float pv = 1.f, Cc = 0.f;
        const float q = (1.0f - ETA_MU) * (1.0f - ETA_MU);
        #pragma unroll
        for (int i = 0; i < L; i++) {
            pv *= q;
            Cc = fmaf(1.0f - ETA_VAR, Cc, ETA_VAR * pv);
        }
        const float dL  = (float)pow((double)(1.0f - ETA_MU),  (double)L);
        const float dvL = (float)pow((double)(1.0f - ETA_VAR), (double)L);

        float m = mu0, v = std0;
        #pragma unroll 8
        for (int c = 0; c < NCHUNK; c++) {
            const int si  = c * CPB + tid;
            const int gi  = c * D + col;
            g_muin [gi] = m;
            g_varin[gi] = v;
            float Sv = fmaf(Cc * m, m, fmaf(-sB[si], m, sA[si]));
            v = fmaf(dvL, v, Sv);
            m = fmaf(dL,  m, sS[si]);
        }
    }
}

#define PC_SMEM_BYTES ((3 * NCHUNK * CPB + 2 * RED_GRP * CPB) * (int)sizeof(float))

// ---------------------------------------------------------------------------
// Pass F: replay each chunk with exact carries; write norm, mu, var (float4,
// streaming loads/stores). out[0..T*D) = norm_x; out[T*D..) = [mu|var] 2D rows.
// ---------------------------------------------------------------------------
__global__ void __launch_bounds__(256) pass_f(const float* __restrict__ x,
                                              float* __restrict__ out) {
    const int col4 = threadIdx.x;
    const int c    = blockIdx.x;
    const int idx4 = c * (D / 4) + col4;

    float4 mu  = ((const float4*)g_muin) [idx4];
    float4 var = ((const float4*)g_varin)[idx4];

    const int t0 = c * L;
    const float4* __restrict__ xp  = (const float4*)(x   + (size_t)t0 * D) + col4;
    float4* __restrict__ nrm       = (float4*)(out + (size_t)t0 * D) + col4;
    float4* __restrict__ info      = (float4*)(out + (size_t)T * D
                                               + (size_t)t0 * (2 * D)) + col4;

    #pragma unroll 4
    for (int i = 0; i < L; i++) {
        float4 xv = __ldcs(&xp[(size_t)i * (D / 4)]);
        float4 nv;
        #define STEP(f)                                                     \
        {                                                                   \
            mu.f  = fmaf(ETA_MU, xv.f - mu.f, mu.f);                        \
            float d2 = xv.f - mu.f;                                         \
            var.f = fmaf(1.0f - ETA_VAR, var.f, ETA_VAR * d2 * d2);         \
            nv.f  = d2 * rsqrtf(var.f);                                     \
        }
        STEP(x) STEP(y) STEP(z) STEP(w)
        #undef STEP
        __stcs(&nrm [(size_t)i * (D / 4)],               nv);
        __stcs(&info[(size_t)i * (2 * D / 4)],           mu);
        __stcs(&info[(size_t)i * (2 * D / 4) + (D / 4)], var);
    }
}

extern "C" void kernel_launch(void* const* d_in, const int* in_sizes, int n_in,
                              void* d_out, int out_size) {
    const float* x = (const float*)d_in[0];
    float* out = (float*)d_out;
    (void)in_sizes; (void)n_in; (void)out_size;

    cudaFuncSetAttribute(pass_c, cudaFuncAttributeMaxDynamicSharedMemorySize,
                         PC_SMEM_BYTES);

    pass_b<<<NCHUNK, 256>>>(x);
    pass_c<<<D / CPB, PC_THREADS, PC_SMEM_BYTES>>>();
    pass_f<<<NCHUNK, 256>>>(x, out);
}

// round 8
// speedup vs baseline: 1.1415x; 1.1415x over previous
#include <cuda_runtime.h>
#include <math.h>

#define T 32768
#define D 1024
#define L 64                  // steps per chunk
#define NCHUNK (T / L)        // 512

#define ETA_MU  0.01f
#define ETA_VAR 0.02f

// Per-(chunk, col) scratch, [chunk][col] layout: 2MB each.
static __device__ float g_sum  [NCHUNK * D];
static __device__ float g_sumsq[NCHUNK * D];
static __device__ float g_smu  [NCHUNK * D];
static __device__ float g_A    [NCHUNK * D];
static __device__ float g_B    [NCHUNK * D];
static __device__ float g_muin [NCHUNK * D];
static __device__ float g_varin[NCHUNK * D];

// ---------------------------------------------------------------------------
// Pass B: one streaming read of x (float4/thread = 4 cols; 256 thr = all of D).
// Per (chunk, col): sum, sumsq (global stats), S_mu (zero-carry local mu scan),
// A, B with  S_var(mu_in) = A - B*mu_in + Cc*mu_in^2  (Cc data-independent).
// ---------------------------------------------------------------------------
__global__ void __launch_bounds__(256) pass_b(const float* __restrict__ x) {
    const int col4 = threadIdx.x;
    const int c    = blockIdx.x;
    const float4* __restrict__ xp =
        (const float4*)(x + (size_t)c * L * D) + col4;

    float4 sum   = {0,0,0,0}, sumsq = {0,0,0,0};
    float4 s     = {0,0,0,0};
    float4 A     = {0,0,0,0}, Bc    = {0,0,0,0};
    float  p     = 1.f;

    #pragma unroll 8
    for (int i = 0; i < L; i++) {
        float4 xv = __ldcs(&xp[(size_t)i * (D / 4)]);
        p *= (1.0f - ETA_MU);
        const float twoEtaP = (2.0f * ETA_VAR) * p;

        #define STEP(f)                                                     \
        {                                                                   \
            sum.f  += xv.f;                                                 \
            sumsq.f = fmaf(xv.f, xv.f, sumsq.f);                            \
            s.f     = fmaf(ETA_MU, xv.f - s.f, s.f);                        \
            float e = xv.f - s.f;                                           \
            A.f     = fmaf(1.0f - ETA_VAR, A.f,  ETA_VAR * e * e);          \
            Bc.f    = fmaf(1.0f - ETA_VAR, Bc.f, twoEtaP * e);              \
        }
        STEP(x) STEP(y) STEP(z) STEP(w)
        #undef STEP
    }
    const int idx4 = c * (D / 4) + col4;
    ((float4*)g_sum)  [idx4] = sum;
    ((float4*)g_sumsq)[idx4] = sumsq;
    ((float4*)g_smu)  [idx4] = s;
    ((float4*)g_A)    [idx4] = A;
    ((float4*)g_B)    [idx4] = Bc;
}

// ---------------------------------------------------------------------------
// Pass C: 64 blocks x 256 threads; block owns 16 columns.
//  1) cooperatively stage A/B/S for its columns into SMEM (96KB)
//  2) parallel sum/sumsq reduction -> mu0, unbiased-std0 (torch.std quirk)
//  3) 16 threads run the serial 512-chunk carry recurrence from SMEM
// ---------------------------------------------------------------------------
#define CPB 16                          // columns per block
#define PC_THREADS 256
#define RED_GRP 16                      // chunk groups for the reduction

__global__ void __launch_bounds__(PC_THREADS) pass_c() {
    extern __shared__ float smem[];
    float* sA   = smem;                         // [NCHUNK][CPB]
    float* sB   = sA + NCHUNK * CPB;
    float* sS   = sB + NCHUNK * CPB;
    float* red  = sS + NCHUNK * CPB;            // [RED_GRP][CPB] x2

    const int tid  = threadIdx.x;
    const int col0 = blockIdx.x * CPB;

    for (int i = tid; i < NCHUNK * CPB; i += PC_THREADS) {
        const int chunk = i / CPB;
        const int lc    = i % CPB;
        const int gidx  = chunk * D + col0 + lc;
        sA[i] = __ldg(&g_A[gidx]);
        sB[i] = __ldg(&g_B[gidx]);
        sS[i] = __ldg(&g_smu[gidx]);
    }

    {
        const int lc  = tid % CPB;
        const int grp = tid / CPB;
        const int cpg = NCHUNK / RED_GRP;
        float ps = 0.f, pq = 0.f;
        for (int c = grp * cpg; c < (grp + 1) * cpg; c++) {
            ps += __ldg(&g_sum  [c * D + col0 + lc]);
            pq += __ldg(&g_sumsq[c * D + col0 + lc]);
        }
        red[grp * CPB + lc]                  = ps;
        red[RED_GRP * CPB + grp * CPB + lc]  = pq;
    }
    __syncthreads();

    if (tid < CPB) {
        const int col = col0 + tid;

        float sum = 0.f, sumsq = 0.f;
        #pragma unroll
        for (int g = 0; g < RED_GRP; g++) {
            sum   += red[g * CPB + tid];
            sumsq += red[RED_GRP * CPB + g * CPB + tid];
        }
        const float mu0  = sum / (float)T;
        const float var0 = (sumsq - sum * mu0) / (float)(T - 1);
        const float std0 = sqrtf(fmaxf(var0, 0.0f));

        // Cc = sum_i 0.98^{L-1-i} * 0.02 * (0.99^{i+1})^2   (constant)
        float pv = 1.f, Cc = 0.f;
        const float q = (1.0f - ETA_MU) * (1.0f - ETA_MU);
        #pragma unroll
        for (int i = 0; i < L; i++) {
            pv *= q;
            Cc = fmaf(1.0f - ETA_VAR, Cc, ETA_VAR * pv);
        }
        const float dL  = (float)pow((double)(1.0f - ETA_MU),  (double)L);
        const float dvL = (float)pow((double)(1.0f - ETA_VAR), (double)L);

        float m = mu0, v = std0;
        #pragma unroll 8
        for (int c = 0; c < NCHUNK; c++) {
            const int si  = c * CPB + tid;
            const int gi  = c * D + col;
            g_muin [gi] = m;
            g_varin[gi] = v;
            float Sv = fmaf(Cc * m, m, fmaf(-sB[si], m, sA[si]));
            v = fmaf(dvL, v, Sv);
            m = fmaf(dL,  m, sS[si]);
        }
    }
}

#define PC_SMEM_BYTES ((3 * NCHUNK * CPB + 2 * RED_GRP * CPB) * (int)sizeof(float))

// ---------------------------------------------------------------------------
// Pass F: replay each chunk with exact carries; write norm, mu, var (float4,
// streaming loads/stores). Reshaped vs R5: 128-thread blocks, grid =
// (NCHUNK chunks) x (2 column halves) = 1024 CTAs, up to 8/SM resident ->
// ~2x in-flight store streams and a 92%-full last wave.
// out[0..T*D) = norm_x; out[T*D..) = [mu|var] rows of 2D.
// ---------------------------------------------------------------------------
__global__ void __launch_bounds__(128, 8) pass_f(const float* __restrict__ x,
                                                 float* __restrict__ out) {
    const int col4 = blockIdx.y * 128 + threadIdx.x;
    const int c    = blockIdx.x;
    const int idx4 = c * (D / 4) + col4;

    float4 mu  = ((const float4*)g_muin) [idx4];
    float4 var = ((const float4*)g_varin)[idx4];

    const int t0 = c * L;
    const float4* __restrict__ xp  = (const float4*)(x   + (size_t)t0 * D) + col4;
    float4* __restrict__ nrm       = (float4*)(out + (size_t)t0 * D) + col4;
    float4* __restrict__ info      = (float4*)(out + (size_t)T * D
                                               + (size_t)t0 * (2 * D)) + col4;

    #pragma unroll 4
    for (int i = 0; i < L; i++) {
        float4 xv = __ldcs(&xp[(size_t)i * (D / 4)]);
        float4 nv;
        #define STEP(f)                                                     \
        {                                                                   \
            mu.f  = fmaf(ETA_MU, xv.f - mu.f, mu.f);                        \
            float d2 = xv.f - mu.f;                                         \
            var.f = fmaf(1.0f - ETA_VAR, var.f, ETA_VAR * d2 * d2);         \
            nv.f  = d2 * rsqrtf(var.f);                                     \
        }
        STEP(x) STEP(y) STEP(z) STEP(w)
        #undef STEP
        __stcs(&nrm [(size_t)i * (D / 4)],               nv);
        __stcs(&info[(size_t)i * (2 * D / 4)],           mu);
        __stcs(&info[(size_t)i * (2 * D / 4) + (D / 4)], var);
    }
}

extern "C" void kernel_launch(void* const* d_in, const int* in_sizes, int n_in,
                              void* d_out, int out_size) {
    const float* x = (const float*)d_in[0];
    float* out = (float*)d_out;
    (void)in_sizes; (void)n_in; (void)out_size;

    cudaFuncSetAttribute(pass_c, cudaFuncAttributeMaxDynamicSharedMemorySize,
                         PC_SMEM_BYTES);

    pass_b<<<NCHUNK, 256>>>(x);
    pass_c<<<D / CPB, PC_THREADS, PC_SMEM_BYTES>>>();
    dim3 grid_f(NCHUNK, 2);
    pass_f<<<grid_f, 128>>>(x, out);
}